// round 17
// baseline (speedup 1.0000x reference)
#include <cuda_runtime.h>
#include <cuda_bf16.h>
#include <cuda_fp16.h>
#include <cstdint>
#include <math.h>

#define NB   2
#define NS   2048
#define NHID 1024
#define NH   16
#define ND   64

#if defined(__CUDA_ARCH__) && (defined(__CUDA_ARCH_FEAT_SM103_ALL) || \
                               defined(__CUDA_ARCH_SPECIFIC__) || \
                               defined(__CUDA_ARCH_FAMILY_SPECIFIC__))
#define USE_TC 1
#else
#define USE_TC 0
#endif

// ---------------- scratch: swizzled 16KB-block buffers (fp16) ----------------
__device__ uint4 g_Aswh[(size_t)3 * 32 * 16 * 1024];   // inputs hi
__device__ uint4 g_Aswl[(size_t)3 * 32 * 16 * 1024];   // inputs lo
__device__ uint4 g_Bswh[(size_t)4 * 8 * 16 * 1024];    // weights hi
__device__ uint4 g_Qswh[(size_t)32 * 16 * 1024];       // Q hi
__device__ uint4 g_Qswl[(size_t)32 * 16 * 1024];       // Q lo
__device__ uint4 g_Kswh[(size_t)32 * 16 * 1024];       // K hi
__device__ uint4 g_Vswh[(size_t)32 * 16 * 1024];       // V^T blocked-atom hi
__device__ uint4 g_Oswh[(size_t)32 * 16 * 1024];       // attn out hi
__device__ uint4 g_Oswl[(size_t)32 * 16 * 1024];       // attn out lo
__device__ float g_rope[(size_t)NS * 64];              // per row: cos[32], sin[32]

__device__ __forceinline__ uint32_t swz128(uint32_t off) { return off ^ ((off >> 3) & 0x70); }

__device__ __forceinline__ void split_hl16(float v, __half& hi, __half& lo) {
    hi = __float2half_rn(v);
    lo = __float2half_rn(v - __half2float(hi));
}
__device__ __forceinline__ uint32_t pack_h2(__half a, __half b) {
    __half2 p = __halves2half2(a, b);
    return *reinterpret_cast<uint32_t*>(&p);
}
__device__ __forceinline__ void pack8_16(const float* v, uint4& hi, uint4& lo) {
    uint32_t h[4], l[4];
    #pragma unroll
    for (int j = 0; j < 4; j++) {
        __half h0, l0, h1, l1;
        split_hl16(v[2 * j], h0, l0);
        split_hl16(v[2 * j + 1], h1, l1);
        h[j] = pack_h2(h0, h1);
        l[j] = pack_h2(l0, l1);
    }
    hi = make_uint4(h[0], h[1], h[2], h[3]);
    lo = make_uint4(l[0], l[1], l[2], l[3]);
}

// ---------------- pre-pass kernels ----------------
__global__ __launch_bounds__(64) void rope_init()
{
    const int s = blockIdx.x;
    const int t = threadIdx.x;
    const int f = t & 31;
    double invf = pow(10000.0, -((double)f) / 32.0);
    float ang = (float)((double)s * invf);
    g_rope[(size_t)s * 64 + t] = (t < 32) ? cosf(ang) : sinf(ang);
}

__global__ __launch_bounds__(256) void convert_in(const float* __restrict__ q,
                                                  const float* __restrict__ k,
                                                  const float* __restrict__ v)
{
    const int i = blockIdx.x * 256 + threadIdx.x;
    const int z = blockIdx.z;
    const float* src = (z == 0) ? q : (z == 1) ? k : v;
    const size_t idx = (size_t)i * 8;
    const int m   = (int)(idx >> 10);
    const int col = (int)(idx & 1023);
    const size_t block = (size_t)(z * 32 + (m >> 7)) * 16 + (col >> 6);
    const uint32_t off = swz128((uint32_t)((m & 127) * 128 + (col & 63) * 2));
    float4 a = reinterpret_cast<const float4*>(src)[2 * i];
    float4 b = reinterpret_cast<const float4*>(src)[2 * i + 1];
    float vv[8] = {a.x, a.y, a.z, a.w, b.x, b.y, b.z, b.w};
    uint4 hi, lo;
    pack8_16(vv, hi, lo);
    *reinterpret_cast<uint4*>(reinterpret_cast<char*>(g_Aswh) + (block << 14) + off) = hi;
    *reinterpret_cast<uint4*>(reinterpret_cast<char*>(g_Aswl) + (block << 14) + off) = lo;
}

__global__ __launch_bounds__(256) void convert_w(const float* __restrict__ wq,
                                                 const float* __restrict__ wk,
                                                 const float* __restrict__ wv,
                                                 const float* __restrict__ wo)
{
    const int i = blockIdx.x * 256 + threadIdx.x;
    const int z = blockIdx.z;
    const float* src = (z == 0) ? wq : (z == 1) ? wk : (z == 2) ? wv : wo;
    const size_t idx = (size_t)i * 8;
    const int m   = (int)(idx >> 10);
    const int col = (int)(idx & 1023);
    const size_t block = (size_t)(z * 8 + (m >> 7)) * 16 + (col >> 6);
    const uint32_t off = swz128((uint32_t)((m & 127) * 128 + (col & 63) * 2));
    float4 a = reinterpret_cast<const float4*>(src)[2 * i];
    float4 b = reinterpret_cast<const float4*>(src)[2 * i + 1];
    uint32_t h[4];
    h[0] = pack_h2(__float2half_rn(a.x), __float2half_rn(a.y));
    h[1] = pack_h2(__float2half_rn(a.z), __float2half_rn(a.w));
    h[2] = pack_h2(__float2half_rn(b.x), __float2half_rn(b.y));
    h[3] = pack_h2(__float2half_rn(b.z), __float2half_rn(b.w));
    *reinterpret_cast<uint4*>(reinterpret_cast<char*>(g_Bswh) + (block << 14) + off) =
        make_uint4(h[0], h[1], h[2], h[3]);
}

// ================= PTX helpers (guarded) =================
#if USE_TC
__device__ __forceinline__ uint32_t smem_u32(const void* p) {
    uint32_t a;
    asm("{ .reg .u64 t; cvta.to.shared.u64 t, %1; cvt.u32.u64 %0, t; }" : "=r"(a) : "l"(p));
    return a;
}
__device__ __forceinline__ void mbar_init(uint32_t addr, uint32_t cnt) {
    asm volatile("mbarrier.init.shared.b64 [%0], %1;" :: "r"(addr), "r"(cnt) : "memory");
}
__device__ __forceinline__ void mbar_inval(uint32_t addr) {
    asm volatile("mbarrier.inval.shared.b64 [%0];" :: "r"(addr) : "memory");
}
__device__ __forceinline__ void mbar_arrive(uint32_t addr) {
    asm volatile("mbarrier.arrive.shared.b64 _, [%0];" :: "r"(addr) : "memory");
}
__device__ __forceinline__ void mbar_wait(uint32_t addr, uint32_t parity) {
    asm volatile(
        "{\n\t.reg .pred P;\n\t"
        "WL%=:\n\t"
        "mbarrier.try_wait.parity.acquire.cta.shared::cta.b64 P, [%0], %1, 0x989680;\n\t"
        "@P bra.uni WD%=;\n\t"
        "bra.uni WL%=;\n\t"
        "WD%=:\n\t}"
        :: "r"(addr), "r"(parity) : "memory");
}
__device__ __forceinline__ void mbar_expect_tx(uint32_t addr, uint32_t bytes) {
    asm volatile("mbarrier.arrive.expect_tx.shared.b64 _, [%0], %1;"
                 :: "r"(addr), "r"(bytes) : "memory");
}
__device__ __forceinline__ void bulk_g2s(uint32_t dst, const void* src, uint32_t bytes,
                                         uint32_t mbar) {
    asm volatile(
        "cp.async.bulk.shared::cluster.global.mbarrier::complete_tx::bytes [%0], [%1], %2, [%3];"
        :: "r"(dst), "l"(src), "r"(bytes), "r"(mbar) : "memory");
}
#define BAR_ARRIVE(id, cnt) asm volatile("bar.arrive %0, %1;" :: "r"(id), "r"(cnt) : "memory")
#define BAR_SYNC(id, cnt)   asm volatile("bar.sync %0, %1;"   :: "r"(id), "r"(cnt) : "memory")
#define TC_ALLOC(smem_addr, ncols) \
    asm volatile("tcgen05.alloc.cta_group::1.sync.aligned.shared::cta.b32 [%0], %1;" \
                 :: "r"(smem_addr), "r"(ncols) : "memory")
#define TC_DEALLOC(tmem, ncols) \
    asm volatile("tcgen05.dealloc.cta_group::1.sync.aligned.b32 %0, %1;" :: "r"(tmem), "r"(ncols))
#define TC_RELINQ() \
    asm volatile("tcgen05.relinquish_alloc_permit.cta_group::1.sync.aligned;")
#define TC_COMMIT(mbar) \
    asm volatile("tcgen05.commit.cta_group::1.mbarrier::arrive::one.shared::cluster.b64 [%0];" \
                 :: "r"(mbar) : "memory")
#define TC_FENCE_AFTER()  asm volatile("tcgen05.fence::after_thread_sync;" ::: "memory")
#define TC_FENCE_BEFORE() asm volatile("tcgen05.fence::before_thread_sync;" ::: "memory")
#define TC_WAIT_LD()      asm volatile("tcgen05.wait::ld.sync.aligned;" ::: "memory")
#define TC_WAIT_ST()      asm volatile("tcgen05.wait::st.sync.aligned;" ::: "memory")

__device__ __forceinline__ void mma_f16_ss(uint32_t d_tmem, uint64_t a_desc, uint64_t b_desc,
                                           uint32_t idesc, bool acc) {
    uint32_t en = acc ? 1u : 0u;
    asm volatile(
        "{\n\t.reg .pred p;\n\t"
        "setp.ne.u32 p, %5, 0;\n\t"
        "tcgen05.mma.cta_group::1.kind::f16 [%0], %1, %2, %3, {%4, %4, %4, %4}, p;\n\t}"
        :: "r"(d_tmem), "l"(a_desc), "l"(b_desc), "r"(idesc), "r"(0u), "r"(en)
        : "memory");
}
__device__ __forceinline__ void mma_f16_ts(uint32_t d_tmem, uint32_t a_tmem, uint64_t b_desc,
                                           uint32_t idesc, bool acc) {
    uint32_t en = acc ? 1u : 0u;
    asm volatile(
        "{\n\t.reg .pred p;\n\t"
        "setp.ne.u32 p, %5, 0;\n\t"
        "tcgen05.mma.cta_group::1.kind::f16 [%0], [%1], %2, %3, {%4, %4, %4, %4}, p;\n\t}"
        :: "r"(d_tmem), "r"(a_tmem), "l"(b_desc), "r"(idesc), "r"(0u), "r"(en)
        : "memory");
}

#define TC_LD_X32(r, tmem_addr) \
    asm volatile( \
        "tcgen05.ld.sync.aligned.32x32b.x32.b32 " \
        "{%0, %1, %2, %3, %4, %5, %6, %7, " \
        " %8, %9, %10, %11, %12, %13, %14, %15, " \
        " %16, %17, %18, %19, %20, %21, %22, %23, " \
        " %24, %25, %26, %27, %28, %29, %30, %31}, [%32];" \
        : "=r"((r)[0]),  "=r"((r)[1]),  "=r"((r)[2]),  "=r"((r)[3]), \
          "=r"((r)[4]),  "=r"((r)[5]),  "=r"((r)[6]),  "=r"((r)[7]), \
          "=r"((r)[8]),  "=r"((r)[9]),  "=r"((r)[10]), "=r"((r)[11]), \
          "=r"((r)[12]), "=r"((r)[13]), "=r"((r)[14]), "=r"((r)[15]), \
          "=r"((r)[16]), "=r"((r)[17]), "=r"((r)[18]), "=r"((r)[19]), \
          "=r"((r)[20]), "=r"((r)[21]), "=r"((r)[22]), "=r"((r)[23]), \
          "=r"((r)[24]), "=r"((r)[25]), "=r"((r)[26]), "=r"((r)[27]), \
          "=r"((r)[28]), "=r"((r)[29]), "=r"((r)[30]), "=r"((r)[31]) \
        : "r"(tmem_addr))

#define TC_ST_X32(tmem_addr, r) \
    asm volatile( \
        "tcgen05.st.sync.aligned.32x32b.x32.b32 [%0], " \
        "{%1, %2, %3, %4, %5, %6, %7, %8, " \
        " %9, %10, %11, %12, %13, %14, %15, %16, " \
        " %17, %18, %19, %20, %21, %22, %23, %24, " \
        " %25, %26, %27, %28, %29, %30, %31, %32};" \
        :: "r"(tmem_addr), \
           "r"((r)[0]),  "r"((r)[1]),  "r"((r)[2]),  "r"((r)[3]), \
           "r"((r)[4]),  "r"((r)[5]),  "r"((r)[6]),  "r"((r)[7]), \
           "r"((r)[8]),  "r"((r)[9]),  "r"((r)[10]), "r"((r)[11]), \
           "r"((r)[12]), "r"((r)[13]), "r"((r)[14]), "r"((r)[15]), \
           "r"((r)[16]), "r"((r)[17]), "r"((r)[18]), "r"((r)[19]), \
           "r"((r)[20]), "r"((r)[21]), "r"((r)[22]), "r"((r)[23]), \
           "r"((r)[24]), "r"((r)[25]), "r"((r)[26]), "r"((r)[27]), \
           "r"((r)[28]), "r"((r)[29]), "r"((r)[30]), "r"((r)[31]) \
        : "memory")

static __device__ __forceinline__ uint64_t make_desc_sw128(uint32_t base_addr) {
    const uint64_t BASE =
        (uint64_t(2)  << 61) | (uint64_t(1) << 46) | (uint64_t(64) << 32) | (uint64_t(1) << 16);
    return BASE | ((uint64_t)(base_addr >> 4) & 0x3FFF);
}
#endif  // USE_TC

// ================= GEMM common =================
#define GEMM_IDESC_F16 ((1u << 4) | (16u << 17) | (8u << 24))
#define ST0       4096
#define GEMM_SMEM (4096 + 3 * 65536)

#if USE_TC
// non-persistent core (used by gemm_wo): 128x(NBLK*128), NSTG stages
template <int NBLK, int NSTG>
__device__ __forceinline__ void gemm_core(uint32_t sbase, uint32_t tmem, int tid,
                                          const char* Ah_base, const char* Al_base,
                                          const char* Bh_base)
{
    const uint32_t STSZ = (uint32_t)(2 + NBLK) * 16384u;
    const uint32_t mbF = sbase + 8;
    const uint32_t mbE = sbase + 8 + 8 * NSTG;
    const uint32_t mbD = sbase + 8 + 16 * NSTG;

    if (tid == 0) {
        int pe[NSTG];
        #pragma unroll
        for (int s = 0; s < NSTG; s++) pe[s] = 0;
        for (int c = 0; c < 16; c++) {
            const int s = c % NSTG;
            if (c >= NSTG) { mbar_wait(mbE + 8 * s, pe[s] & 1); pe[s]++; }
            const uint32_t dst = sbase + ST0 + s * STSZ;
            const uint32_t mb = mbF + 8 * s;
            mbar_expect_tx(mb, STSZ);
            bulk_g2s(dst +     0, Ah_base + ((size_t)c << 14), 16384, mb);
            bulk_g2s(dst + 16384, Al_base + ((size_t)c << 14), 16384, mb);
            #pragma unroll
            for (int nb = 0; nb < NBLK; nb++)
                bulk_g2s(dst + 32768 + nb * 16384,
                         Bh_base + ((size_t)(nb * 16 + c) << 14), 16384, mb);
        }
    } else if (tid == 32) {
        int pf[NSTG];
        #pragma unroll
        for (int s = 0; s < NSTG; s++) pf[s] = 0;
        for (int c = 0; c < 16; c++) {
            const int s = c % NSTG;
            mbar_wait(mbF + 8 * s, pf[s] & 1); pf[s]++;
            const uint32_t stg = sbase + ST0 + s * STSZ;
            const uint64_t ah  = make_desc_sw128(stg);
            const uint64_t al  = make_desc_sw128(stg + 16384);
            #pragma unroll
            for (int ks = 0; ks < 4; ks++) {
                const uint64_t o = (uint64_t)(ks * 2);
                const bool first = (c == 0 && ks == 0);
                #pragma unroll
                for (int nb = 0; nb < NBLK; nb++) {
                    const uint64_t bh = make_desc_sw128(stg + 32768 + nb * 16384);
                    mma_f16_ss(tmem + nb * 128, ah + o, bh + o, GEMM_IDESC_F16, !first);
                    mma_f16_ss(tmem + nb * 128, al + o, bh + o, GEMM_IDESC_F16, true);
                }
            }
            TC_COMMIT(mbE + 8 * s);
        }
        TC_COMMIT(mbD);
    }
    mbar_wait(mbD, 0);
    TC_FENCE_AFTER();
}
#endif

// ===== persistent QKV projections: 148 CTAs x 192 threads, 384 tiles (N=256) =====
// tile t: mode = t>>7, bx = (t&127)>>2, by = t&3.
// warps 0-3: epilogue; tid 128: producer; tid 160: MMA issuer.
// TMEM: D double buffer @0 and @256 (512 cols).
__global__ __launch_bounds__(192, 1) void gemm_qkv_pers(const float* __restrict__ bq,
                                                        const float* __restrict__ bk,
                                                        const float* __restrict__ bv)
{
    extern __shared__ char smem[];
#if USE_TC
    const int cta = blockIdx.x;
    const int tid = threadIdx.x;
    const uint32_t sbase = smem_u32(smem);
    const int wid = tid >> 5;

    // mbars: full[3]@+8, empty[3]@+32, tileD[2]@+56, epiE[2]@+72
    if (wid == 0) TC_ALLOC(sbase, 512);
    if (tid == 0) {
        #pragma unroll
        for (int s = 0; s < 3; s++) { mbar_init(sbase + 8 + 8 * s, 1); mbar_init(sbase + 32 + 8 * s, 1); }
        mbar_init(sbase + 56, 1); mbar_init(sbase + 64, 1);
        mbar_init(sbase + 72, 512); mbar_init(sbase + 80, 512);   // 128 thr x 4 blocks
    }
    __syncthreads();
    uint32_t tmem;
    asm volatile("ld.shared.b32 %0, [%1];" : "=r"(tmem) : "r"(sbase));

    if (tid == 128) {
        // -------- producer: continuous bulk-copy stream over all my tiles --------
        int g = 0;
        int pe[3] = {0, 0, 0};
        for (int tl = 0;; tl++) {
            const int tile = cta + tl * 148;
            if (tile >= 384) break;
            const int mode = tile >> 7;
            const int rem  = tile & 127;
            const int bx = rem >> 2, by = rem & 3;
            const char* Ah = reinterpret_cast<const char*>(g_Aswh) +
                             (((size_t)(mode * 32 + bx) * 16) << 14);
            const char* Al = reinterpret_cast<const char*>(g_Aswl) +
                             (((size_t)(mode * 32 + bx) * 16) << 14);
            const char* Bh = reinterpret_cast<const char*>(g_Bswh) +
                             (((size_t)(mode * 8 + by * 2) * 16) << 14);
            for (int c = 0; c < 16; c++) {
                const int s = g % 3;
                if (g >= 3) { mbar_wait(sbase + 32 + 8 * s, pe[s] & 1); pe[s]++; }
                const uint32_t dst = sbase + ST0 + s * 65536;
                const uint32_t mb = sbase + 8 + 8 * s;
                mbar_expect_tx(mb, 65536);
                bulk_g2s(dst +     0, Ah + ((size_t)c << 14), 16384, mb);
                bulk_g2s(dst + 16384, Al + ((size_t)c << 14), 16384, mb);
                bulk_g2s(dst + 32768, Bh + ((size_t)c << 14), 16384, mb);
                bulk_g2s(dst + 49152, Bh + ((size_t)(c + 16) << 14), 16384, mb);
                g++;
            }
        }
    } else if (tid == 160) {
        // -------- MMA issuer --------
        int g = 0;
        int pf[3] = {0, 0, 0};
        int pd[2] = {0, 0};
        for (int tl = 0;; tl++) {
            const int tile = cta + tl * 148;
            if (tile >= 384) break;
            const int buf = tl & 1;
            if (tl >= 2) {   // wait for epilogue to finish reading this D buffer
                mbar_wait(sbase + 72 + 8 * buf, pd[buf] & 1); pd[buf]++;
                TC_FENCE_AFTER();
            }
            const uint32_t dt = tmem + buf * 256;
            for (int c = 0; c < 16; c++) {
                const int s = g % 3;
                mbar_wait(sbase + 8 + 8 * s, pf[s] & 1); pf[s]++;
                const uint32_t stg = sbase + ST0 + s * 65536;
                const uint64_t ah  = make_desc_sw128(stg);
                const uint64_t al  = make_desc_sw128(stg + 16384);
                const uint64_t bh0 = make_desc_sw128(stg + 32768);
                const uint64_t bh1 = make_desc_sw128(stg + 49152);
                #pragma unroll
                for (int ks = 0; ks < 4; ks++) {
                    const uint64_t o = (uint64_t)(ks * 2);
                    const bool first = (c == 0 && ks == 0);
                    mma_f16_ss(dt,       ah + o, bh0 + o, GEMM_IDESC_F16, !first);
                    mma_f16_ss(dt,       al + o, bh0 + o, GEMM_IDESC_F16, true);
                    mma_f16_ss(dt + 128, ah + o, bh1 + o, GEMM_IDESC_F16, !first);
                    mma_f16_ss(dt + 128, al + o, bh1 + o, GEMM_IDESC_F16, true);
                }
                TC_COMMIT(sbase + 32 + 8 * s);   // release stage
                g++;
            }
            TC_COMMIT(sbase + 56 + 8 * buf);     // D ready
        }
    } else if (tid < 128) {
        // -------- epilogue warps 0-3 --------
        int pt[2] = {0, 0};
        const int lane = tid & 31;
        const int ew = wid;                      // 0..3, TMEM subpartition
        for (int tl = 0;; tl++) {
            const int tile = cta + tl * 148;
            if (tile >= 384) break;
            const int mode = tile >> 7;
            const int rem  = tile & 127;
            const int bx = rem >> 2, by = rem & 3;
            const int buf = tl & 1;
            const int m0 = bx * 128, n0 = by * 256;
            const float* bias = (mode == 0) ? bq : (mode == 1) ? bk : bv;
            const int m  = m0 + ew * 32 + lane;
            const int bb = m >> 11;
            const int s_ = m & 2047;

            mbar_wait(sbase + 56 + 8 * buf, pt[buf] & 1); pt[buf]++;
            TC_FENCE_AFTER();

            float cs[64];
            if (mode < 2) {
                const float4* rp = reinterpret_cast<const float4*>(g_rope + (size_t)s_ * 64);
                #pragma unroll
                for (int j = 0; j < 16; j++)
                    *reinterpret_cast<float4*>(&cs[4 * j]) = __ldg(rp + j);
            }
            #pragma unroll
            for (int it = 0; it < 4; it++) {
                uint32_t dr[64];
                TC_LD_X32(dr, tmem + buf * 256 + it * 64);
                TC_LD_X32(dr + 32, tmem + buf * 256 + it * 64 + 32);
                TC_WAIT_LD();
                mbar_arrive(sbase + 72 + 8 * buf);   // block consumed into regs
                float v[64];
                #pragma unroll
                for (int j = 0; j < 64; j++)
                    v[j] = __uint_as_float(dr[j]) + __ldg(bias + n0 + it * 64 + j);

                const int h  = by * 4 + it;
                const int bh = bb * NH + h;
                if (mode < 2) {
                    float w[64];
                    #pragma unroll
                    for (int dcol = 0; dcol < 64; dcol++) {
                        const int f = dcol & 31;
                        float rot = (dcol < 32) ? -v[2 * dcol + 1] : v[2 * (dcol - 32)];
                        w[dcol] = v[dcol] * cs[f] + rot * cs[32 + f];
                    }
                    const int r = s_ & 127;
                    if (mode == 0) {
                        uint32_t hw[32], lw[32];
                        #pragma unroll
                        for (int j = 0; j < 32; j++) {
                            __half h0, l0, h1, l1;
                            split_hl16(w[2 * j], h0, l0);
                            split_hl16(w[2 * j + 1], h1, l1);
                            hw[j] = pack_h2(h0, h1);
                            lw[j] = pack_h2(l0, l1);
                        }
                        char* dh = reinterpret_cast<char*>(g_Qswh) +
                                   (((size_t)bh * 16 + (s_ >> 7)) << 14);
                        char* dl = reinterpret_cast<char*>(g_Qswl) +
                                   (((size_t)bh * 16 + (s_ >> 7)) << 14);
                        #pragma unroll
                        for (int j = 0; j < 8; j++) {
                            const uint32_t o = swz128((uint32_t)(r * 128 + j * 16));
                            *reinterpret_cast<uint4*>(dh + o) =
                                make_uint4(hw[4*j], hw[4*j+1], hw[4*j+2], hw[4*j+3]);
                            *reinterpret_cast<uint4*>(dl + o) =
                                make_uint4(lw[4*j], lw[4*j+1], lw[4*j+2], lw[4*j+3]);
                        }
                    } else {
                        uint32_t hw[32];
                        #pragma unroll
                        for (int j = 0; j < 32; j++)
                            hw[j] = pack_h2(__float2half_rn(w[2 * j]),
                                            __float2half_rn(w[2 * j + 1]));
                        char* dh = reinterpret_cast<char*>(g_Kswh) +
                                   (((size_t)bh * 16 + (s_ >> 7)) << 14);
                        #pragma unroll
                        for (int j = 0; j < 8; j++) {
                            const uint32_t o = swz128((uint32_t)(r * 128 + j * 16));
                            *reinterpret_cast<uint4*>(dh + o) =
                                make_uint4(hw[4*j], hw[4*j+1], hw[4*j+2], hw[4*j+3]);
                        }
                    }
                } else {
                    char* dh = reinterpret_cast<char*>(g_Vswh) +
                               (((size_t)bh * 16 + (s_ >> 7)) << 14);
                    const int key = s_ & 127;
                    const uint32_t kpart = (uint32_t)((key >> 6) * 8 * 1024 +
                                                      ((key >> 3) & 7) * 16 + (key & 7) * 2);
                    #pragma unroll
                    for (int dcol = 0; dcol < 64; dcol++) {
                        const uint32_t byte =
                            swz128((uint32_t)((dcol >> 3) * 1024 + (dcol & 7) * 128) + kpart);
                        *reinterpret_cast<__half*>(dh + byte) = __float2half_rn(v[dcol]);
                    }
                }
            }
            TC_FENCE_BEFORE();
        }
    }

    __syncthreads();
    if (tid == 0) {
        #pragma unroll
        for (int s = 0; s < 3; s++) { mbar_inval(sbase + 8 + 8 * s); mbar_inval(sbase + 32 + 8 * s); }
        mbar_inval(sbase + 56); mbar_inval(sbase + 64);
        mbar_inval(sbase + 72); mbar_inval(sbase + 80);
    }
    __syncthreads();
    if (wid == 0) { TC_RELINQ(); TC_DEALLOC(tmem, 512); }
#else
    (void)bq; (void)bk; (void)bv;
#endif
}

// Output projection: 128x256 tiles, 3-stage (non-persistent; 0.87 waves)
__global__ __launch_bounds__(256, 1) void gemm_wo(const float* __restrict__ bias,
                                                  float* __restrict__ Yext)
{
    extern __shared__ char smem[];
#if USE_TC
    const int bx = blockIdx.x;
    const int by = blockIdx.y;
    const int m0 = bx * 128;
    const int n0 = by * 256;
    const int tid = threadIdx.x;
    const uint32_t sbase = smem_u32(smem);
    const int wid = tid >> 5;
    const int lane = tid & 31;
    float* sbias = reinterpret_cast<float*>(smem + 1024);

    if (wid == 0) TC_ALLOC(sbase, 256);
    if (tid == 0) {
        #pragma unroll
        for (int s = 0; s < 3; s++) {
            mbar_init(sbase + 8 + 8 * s, 1);
            mbar_init(sbase + 32 + 8 * s, 1);
        }
        mbar_init(sbase + 56, 1);
    }
    sbias[tid] = __ldg(bias + n0 + tid);
    __syncthreads();
    uint32_t tmem;
    asm volatile("ld.shared.b32 %0, [%1];" : "=r"(tmem) : "r"(sbase));

    const char* Ah_base = reinterpret_cast<const char*>(g_Oswh) + (((size_t)bx * 16) << 14);
    const char* Al_base = reinterpret_cast<const char*>(g_Oswl) + (((size_t)bx * 16) << 14);
    const char* Bh_base = reinterpret_cast<const char*>(g_Bswh) + (((size_t)(24 + by * 2) * 16) << 14);

    gemm_core<2, 3>(sbase, tmem, tid, Ah_base, Al_base, Bh_base);

    {
        const int m = m0 + (wid & 3) * 32 + lane;
        #pragma unroll
        for (int it = 0; it < 2; it++) {
            const int hb = (wid >> 2) * 2 + it;
            uint32_t dr[64];
            TC_LD_X32(dr, tmem + hb * 64);
            TC_LD_X32(dr + 32, tmem + hb * 64 + 32);
            TC_WAIT_LD();
            float* orow = Yext + (size_t)m * NHID + n0 + hb * 64;
            #pragma unroll
            for (int j = 0; j < 16; j++) {
                float v0 = __uint_as_float(dr[4*j+0]) + sbias[hb * 64 + 4*j+0];
                float v1 = __uint_as_float(dr[4*j+1]) + sbias[hb * 64 + 4*j+1];
                float v2 = __uint_as_float(dr[4*j+2]) + sbias[hb * 64 + 4*j+2];
                float v3 = __uint_as_float(dr[4*j+3]) + sbias[hb * 64 + 4*j+3];
                *reinterpret_cast<float4*>(orow + j * 4) = make_float4(v0, v1, v2, v3);
            }
        }
        TC_FENCE_BEFORE();
    }
    __syncthreads();
    if (tid == 0) {
        #pragma unroll
        for (int s = 0; s < 3; s++) { mbar_inval(sbase + 8 + 8 * s); mbar_inval(sbase + 32 + 8 * s); }
        mbar_inval(sbase + 56);
    }
    __syncthreads();
    if (wid == 0) { TC_RELINQ(); TC_DEALLOC(tmem, 256); }
#else
    (void)bias; (void)Yext;
#endif
}

// ================= flash attention (TMEM 256, 2 CTAs/SM) — unchanged R15 =================
#define FA_QH    0
#define FA_QL    16384
#define FA_ST0   32768
#define FA_STSZ  32768
#define FA_REL   98304
#define FA_RS    100352
#define FA_CTRL  101376
#define FA_SMEM  101440

#define TM_S  0
#define TM_O  128
#define TM_P  192

#define IDESC_QK_F16 ((1u << 4) | (16u << 17) | (8u << 24))
#define IDESC_PV     ((1u << 4) | (8u << 17)  | (8u << 24))

__global__ __launch_bounds__(288, 2) void flash_attn(const float* __restrict__ rel)
{
    extern __shared__ char smem[];
#if USE_TC
    const int bid = blockIdx.x;
    const int qt = 15 - (bid >> 5);
    const int bh = bid & 31;
    const int h  = bh & (NH - 1);
    const int q0 = qt * 128;
    const int tid = threadIdx.x;
    const uint32_t sbase = smem_u32(smem);
    const int wid = tid >> 5;
    const uint32_t ctrl = sbase + FA_CTRL;
    const uint32_t mbQ  = ctrl + 8;
    const uint32_t kvf0 = ctrl + 16;
    const uint32_t mb0  = ctrl + 32;
    const uint32_t mb1  = ctrl + 40;
    const uint32_t mbd  = ctrl + 48;
    float* rs = reinterpret_cast<float*>(smem + FA_RS);

    if (wid == 0) TC_ALLOC(ctrl, 256);
    if (tid == 0) {
        mbar_init(mbQ, 1);
        mbar_init(kvf0, 1); mbar_init(kvf0 + 8, 1);
        mbar_init(mb0, 1);  mbar_init(mb1, 1); mbar_init(mbd, 1);
    }
    __syncthreads();

    uint32_t tmem;
    asm volatile("ld.shared.b32 %0, [%1];" : "=r"(tmem) : "r"(ctrl));

    const char* Qh_src = reinterpret_cast<const char*>(g_Qswh) + (((size_t)bh * 16 + qt) << 14);
    const char* Ql_src = reinterpret_cast<const char*>(g_Qswl) + (((size_t)bh * 16 + qt) << 14);
    const char* Kh_b = reinterpret_cast<const char*>(g_Kswh) + (((size_t)bh * 16) << 14);
    const char* Vh_b = reinterpret_cast<const char*>(g_Vswh) + (((size_t)bh * 16) << 14);

    const uint64_t dqh = make_desc_sw128(sbase + FA_QH);
    const uint64_t dql = make_desc_sw128(sbase + FA_QL);

    if (wid == 8) {
        if (tid == 256) {
            mbar_expect_tx(mbQ, 32768);
            bulk_g2s(sbase + FA_QH, Qh_src, 16384, mbQ);
            bulk_g2s(sbase + FA_QL, Ql_src, 16384, mbQ);
            mbar_expect_tx(kvf0, 32768);
            bulk_g2s(sbase + FA_ST0 +     0, Kh_b, 16384, kvf0);
            bulk_g2s(sbase + FA_ST0 + 16384, Vh_b, 16384, kvf0);
            mbar_wait(mbQ, 0);
            mbar_wait(kvf0, 0);
            const uint64_t dkh = make_desc_sw128(sbase + FA_ST0);
            #pragma unroll
            for (int ks = 0; ks < 4; ks++) {
                const uint64_t o = (uint64_t)(ks * 2);
                mma_f16_ss(tmem + TM_S, dqh + o, dkh + o, IDESC_QK_F16, ks > 0);
                mma_f16_ss(tmem + TM_S, dql + o, dkh + o, IDESC_QK_F16, true);
            }
            TC_COMMIT(mb0);
        }
        int ph1 = 0;
        int pkv[2] = {1, 0};
        for (int kt = 0; kt <= qt; kt++) {
            if (tid == 256) {
                if (kt > 0) { mbar_wait(mb1, ph1 & 1); ph1++; }
                if (kt + 1 <= qt) {
                    const int sn = (kt + 1) & 1;
                    const uint32_t dst = sbase + FA_ST0 + sn * FA_STSZ;
                    const uint32_t mbn = kvf0 + 8 * sn;
                    const size_t o = (size_t)(kt + 1) << 14;
                    mbar_expect_tx(mbn, 32768);
                    bulk_g2s(dst +     0, Kh_b + o, 16384, mbn);
                    bulk_g2s(dst + 16384, Vh_b + o, 16384, mbn);
                }
            }
            BAR_SYNC(1, 288);
            if (tid == 256 && kt + 1 <= qt) {
                const int sn = (kt + 1) & 1;
                mbar_wait(kvf0 + 8 * sn, pkv[sn] & 1); pkv[sn]++;
                const uint64_t dkh = make_desc_sw128(sbase + FA_ST0 + sn * FA_STSZ);
                #pragma unroll
                for (int ks = 0; ks < 4; ks++) {
                    const uint64_t o = (uint64_t)(ks * 2);
                    mma_f16_ss(tmem + TM_S, dqh + o, dkh + o, IDESC_QK_F16, ks > 0);
                    mma_f16_ss(tmem + TM_S, dql + o, dkh + o, IDESC_QK_F16, true);
                }
                TC_COMMIT(mb0);
            }
            BAR_SYNC(2, 288);
            if (tid == 256) {
                TC_FENCE_AFTER();
                const uint64_t dvh = make_desc_sw128(sbase + FA_ST0 + (kt & 1) * FA_STSZ + 16384);
                #pragma unroll
                for (int ks = 0; ks < 8; ks++) {
                    const uint64_t bo = (ks < 4) ? (uint64_t)(ks * 2)
                                                 : (uint64_t)(512 + (ks - 4) * 2);
                    mma_f16_ts(tmem + TM_O, tmem + TM_P + (uint32_t)(ks * 8), dvh + bo,
                               IDESC_PV, !(kt == 0 && ks == 0));
                }
                TC_COMMIT(mb1);
            }
        }
        if (tid == 256) TC_COMMIT(mbd);
    } else {
        const int half = wid >> 2;
        const int sub  = wid & 3;
        const int lane = tid & 31;
        const int row  = sub * 32 + lane;
        const int colbase = half * 64;
        const uint32_t woff = ((uint32_t)sub) << 21;
        float rowsum = 0.f;
        uint32_t phs = 0;
        uint32_t phm = 0;

        for (int kt = 0; kt <= qt; kt++) {
            float* relbuf = reinterpret_cast<float*>(smem + FA_REL + (kt & 1) * 1024);
            if (tid < 255)
                relbuf[tid] = __ldg(rel + (size_t)(q0 - kt * 128 - 127 + tid + 2047) * NH + h);
            BAR_SYNC(3, 256);
            mbar_wait(mb0, phs); phs ^= 1;
            TC_FENCE_AFTER();
            const bool diag = (kt == qt);
            uint32_t pr[32];
            #pragma unroll
            for (int qtr = 0; qtr < 2; qtr++) {
                uint32_t sr[32];
                TC_LD_X32(sr, tmem + TM_S + colbase + qtr * 32);
                TC_WAIT_LD();
                #pragma unroll
                for (int j = 0; j < 16; j++) {
                    float p0, p1;
                    {
                        const int col = colbase + qtr * 32 + 2 * j;
                        float sc = __uint_as_float(sr[2*j]) * 0.125f + relbuf[127 + row - col];
                        p0 = __expf(sc);
                        if (diag && col > row) p0 = 0.f;
                    }
                    {
                        const int col = colbase + qtr * 32 + 2 * j + 1;
                        float sc = __uint_as_float(sr[2*j+1]) * 0.125f + relbuf[127 + row - col];
                        p1 = __expf(sc);
                        if (diag && col > row) p1 = 0.f;
                    }
                    rowsum += p0 + p1;
                    __half2 hp = __floats2half2_rn(p0, p1);
                    pr[qtr * 16 + j] = *reinterpret_cast<uint32_t*>(&hp);
                }
            }
            BAR_ARRIVE(1, 288);
            if (kt > 0) { mbar_wait(mb1, phm); phm ^= 1; }
            TC_ST_X32(tmem + TM_P + half * 32 + woff, pr);
            TC_WAIT_ST();
            TC_FENCE_BEFORE();
            BAR_ARRIVE(2, 288);
        }
        rs[half * 128 + row] = rowsum;
    }

    mbar_wait(mbd, 0);
    TC_FENCE_AFTER();
    __syncthreads();

    if (wid < 8) {
        const int half = wid >> 2;
        const int sub  = wid & 3;
        const int lane = tid & 31;
        const int row  = sub * 32 + lane;
        uint32_t orr[32];
        TC_LD_X32(orr, tmem + TM_O + half * 32);
        TC_WAIT_LD();
        TC_FENCE_BEFORE();
        const float inv = 1.0f / (rs[row] + rs[128 + row]);
        const int iq = q0 + row;
        const int b = bh >> 4;
        const int m = b * NS + iq;
        uint32_t hw[16], lw[16];
        #pragma unroll
        for (int j = 0; j < 16; j++) {
            float v0 = fminf(30.f, fmaxf(-30.f, __uint_as_float(orr[2*j])   * inv));
            float v1 = fminf(30.f, fmaxf(-30.f, __uint_as_float(orr[2*j+1]) * inv));
            __half h0, l0, h1, l1;
            split_hl16(v0, h0, l0);
            split_hl16(v1, h1, l1);
            hw[j] = pack_h2(h0, h1);
            lw[j] = pack_h2(l0, l1);
        }
        char* dh = reinterpret_cast<char*>(g_Oswh) + (((size_t)(m >> 7) * 16 + h) << 14);
        char* dl = reinterpret_cast<char*>(g_Oswl) + (((size_t)(m >> 7) * 16 + h) << 14);
        const int r = m & 127;
        #pragma unroll
        for (int j = 0; j < 4; j++) {
            const uint32_t o = swz128((uint32_t)(r * 128 + half * 64 + j * 16));
            *reinterpret_cast<uint4*>(dh + o) =
                make_uint4(hw[4*j], hw[4*j+1], hw[4*j+2], hw[4*j+3]);
            *reinterpret_cast<uint4*>(dl + o) =
                make_uint4(lw[4*j], lw[4*j+1], lw[4*j+2], lw[4*j+3]);
        }
    }

    __syncthreads();
    if (tid == 0) {
        mbar_inval(mbQ);
        mbar_inval(kvf0); mbar_inval(kvf0 + 8);
        mbar_inval(mb0);  mbar_inval(mb1); mbar_inval(mbd);
    }
    __syncthreads();
    if (wid == 0) { TC_RELINQ(); TC_DEALLOC(tmem, 256); }
#else
    (void)rel;
#endif
}

// ---------------- launch ----------------
extern "C" void kernel_launch(void* const* d_in, const int* in_sizes, int n_in,
                              void* d_out, int out_size)
{
    (void)in_sizes; (void)n_in; (void)out_size;
    const float* q_in = (const float*)d_in[0];
    const float* k_in = (const float*)d_in[1];
    const float* v_in = (const float*)d_in[2];
    const float* wq = (const float*)d_in[4];
    const float* bq = (const float*)d_in[5];
    const float* wk = (const float*)d_in[6];
    const float* bk = (const float*)d_in[7];
    const float* wv = (const float*)d_in[8];
    const float* bv = (const float*)d_in[9];
    const float* wo = (const float*)d_in[10];
    const float* bo = (const float*)d_in[11];
    const float* rel = (const float*)d_in[12];
    float* out = (float*)d_out;

    cudaFuncSetAttribute(gemm_qkv_pers, cudaFuncAttributeMaxDynamicSharedMemorySize, GEMM_SMEM);
    cudaFuncSetAttribute(gemm_wo,  cudaFuncAttributeMaxDynamicSharedMemorySize, GEMM_SMEM);
    cudaFuncSetAttribute(flash_attn, cudaFuncAttributeMaxDynamicSharedMemorySize, FA_SMEM);

    rope_init<<<NS, 64>>>();
    convert_in<<<dim3(2048, 1, 3), 256>>>(q_in, k_in, v_in);
    convert_w<<<dim3(512, 1, 4), 256>>>(wq, wk, wv, wo);

    gemm_qkv_pers<<<148, 192, GEMM_SMEM>>>(bq, bk, bv);
    flash_attn<<<512, 288, FA_SMEM>>>(rel);
    gemm_wo<<<dim3(32, 4), 256, GEMM_SMEM>>>(bo, out);
}